// round 3
// baseline (speedup 1.0000x reference)
#include <cuda_runtime.h>
#include <cstdint>

// ReadoutLayer: out[b,d] = sum_n h[b,n,d] * (op_idx[b,n] != 5)
// B=4096, N=64, D=256 fp32; op_idx int32 (JAX x64 disabled).
//
// R2: 45.1us @ DRAM 76.5% with smem-reduce layout.
// R3: one thread owns one float4 column across all 64 rows -> no partial
//     reduce, one barrier, balanced stores; __ldcs evict-first streaming.
// 1024 CTAs x 256 thr; CTA = 4 graphs x 64 float4 columns.

#define SKIP_OP 5

__global__ __launch_bounds__(256, 8)
void readout_kernel(const float4* __restrict__ h,   // [B, 64, 64] float4
                    const int* __restrict__ op,     // [B, 64] int32
                    float4* __restrict__ out)       // [B, 64] float4
{
    __shared__ float smask[256];                    // 4 graphs x 64 nodes

    const int tid = threadIdx.x;
    const int b0  = blockIdx.x << 2;                // first graph of this CTA

    // Stage all 4 graphs' masks (one int32 per thread, 1KB contiguous).
    smask[tid] = (op[(size_t)b0 * 64 + tid] != SKIP_OP) ? 1.0f : 0.0f;
    __syncthreads();

    const int g = tid >> 6;                         // graph within CTA (0..3)
    const int v = tid & 63;                         // float4 column (0..63)
    const int b = b0 + g;

    const float4* base = h + (size_t)b * 64 * 64 + v;   // row stride 64 float4
    const float*  mk   = smask + (g << 6);

    float4 acc = make_float4(0.f, 0.f, 0.f, 0.f);

#pragma unroll
    for (int row = 0; row < 64; ++row) {
        const float  m = mk[row];                   // warp-uniform broadcast
        const float4 x = __ldcs(base + (size_t)row * 64);  // evict-first stream
        acc.x = fmaf(m, x.x, acc.x);
        acc.y = fmaf(m, x.y, acc.y);
        acc.z = fmaf(m, x.z, acc.z);
        acc.w = fmaf(m, x.w, acc.w);
    }

    out[(size_t)b * 64 + v] = acc;
}

extern "C" void kernel_launch(void* const* d_in, const int* in_sizes, int n_in,
                              void* d_out, int out_size)
{
    const float4* h  = (const float4*)d_in[0];  // node_embeddings [4096,64,256] f32
    const int*    op = (const int*)d_in[1];     // op_idx [4096,64] int32
    float4*       o  = (float4*)d_out;          // [4096,256] f32

    const int B = in_sizes[1] / 64;             // 4096
    readout_kernel<<<B / 4, 256>>>(h, op, o);
}